// round 2
// baseline (speedup 1.0000x reference)
#include <cuda_runtime.h>
#include <cstdint>
#include <cstddef>

// Problem constants
#define B_    32
#define S_    2048
#define C_    7
#define O_    512
#define KI    56      // 56 input features (c*8+m)
#define KH    3       // conv taps
#define KK    168     // KI*KH
#define TAO_  24
#define MT    168     // M*TAO zero-pad region
// Tiling
#define TT    128     // t per CTA
#define OC    128     // o per chunk
#define NCH   (O_/OC) // 4 chunks
#define ZSTR  132     // zs row stride (floats), 16B-aligned rows
#define NTHREADS 256

// Transposed weights: g_Wt[k*512 + o] = W[o*168 + k]
__device__ float g_Wt[KK * O_];

__global__ void wt_transpose_kernel(const float* __restrict__ W) {
    int gid = blockIdx.x * blockDim.x + threadIdx.x;
    if (gid < KK * O_) {
        int k = gid >> 9;        // / 512
        int o = gid & (O_ - 1);  // % 512
        g_Wt[gid] = W[o * KK + k];
    }
}

#define PACK2(d, lo, hi)  asm("mov.b64 %0, {%1, %2};" : "=l"(d) : "f"(lo), "f"(hi))
#define UNPACK2(lo, hi, s) asm("mov.b64 {%0, %1}, %2;" : "=f"(lo), "=f"(hi) : "l"(s))
#define FMA2(acc, a, w)   asm("fma.rn.f32x2 %0, %1, %2, %0;" : "+l"(acc) : "l"(a), "l"(w))

__global__ __launch_bounds__(NTHREADS, 1)
void conv_main_kernel(const float* __restrict__ x,
                      const float* __restrict__ bias,
                      float* __restrict__ out) {
    extern __shared__ float smem[];
    float* zs = smem;                 // [KI][ZSTR]   29568 B
    float* Ws = smem + KI * ZSTR;     // [KK][OC]     86016 B

    const int tid = threadIdx.x;
    // ty minor within warp -> coalesced stores + broadcast zs reads
    const int ty = tid & 15;   // o-group: 16 groups x 8 o = 128 o
    const int tx = tid >> 4;   // t-group: 16 groups x 8 t = 128 t
    const int t0 = blockIdx.x * TT;
    const int bb = blockIdx.y;
    const float* xb = x + (size_t)bb * S_ * C_;

    // ---- stage z tile: zs[i][tt] = z[bb, i, t0-1+tt], tt in [0,130) ----
    for (int idx = tid; idx < KI * (TT + 2); idx += NTHREADS) {
        int i  = idx / (TT + 2);
        int tt = idx - i * (TT + 2);
        int c  = i >> 3;
        int m  = i & 7;
        int s  = t0 - 1 + tt;
        int sm = s & (S_ - 1);          // wrap (handles s=-1 and s=2048)
        float v = 0.0f;
        if (sm >= MT) v = __ldg(&xb[(sm - TAO_ * m) * C_ + c]);
        zs[i * ZSTR + tt] = v;
    }
    __syncthreads();

    const float4* zs4 = (const float4*)zs;
    const float4* Ws4 = (const float4*)Ws;
    const float4* Wt4 = (const float4*)g_Wt;

    for (int och = 0; och < NCH; ++och) {
        // ---- stage W chunk: Ws[k][0..127] = g_Wt[k][och*128 .. +127] ----
        // 168 rows x 32 float4; coalesced LDG + conflict-free STS
        for (int idx = tid; idx < KK * (OC / 4); idx += NTHREADS) {
            int k = idx >> 5;
            int f = idx & 31;
            ((float4*)Ws)[idx] = __ldg(&Wt4[k * (O_ / 4) + och * (OC / 4) + f]);
        }
        __syncthreads();

        // ---- compute: 8t x 8o per thread, f32x2 packed accumulators ----
        unsigned long long acc[8][4];
        #pragma unroll
        for (int j = 0; j < 8; ++j) {
            #pragma unroll
            for (int p = 0; p < 4; ++p) acc[j][p] = 0ULL;
        }

        const int zbase = 2 * tx;  // float4 index within zs row
        #pragma unroll 1
        for (int i = 0; i < KI; ++i) {
            float4 va = zs4[i * (ZSTR / 4) + zbase];
            float4 vb = zs4[i * (ZSTR / 4) + zbase + 1];
            float4 vc = zs4[i * (ZSTR / 4) + zbase + 2];
            float v[12] = { va.x, va.y, va.z, va.w,
                            vb.x, vb.y, vb.z, vb.w,
                            vc.x, vc.y, vc.z, vc.w };
            #pragma unroll
            for (int h = 0; h < KH; ++h) {
                int k = i * 3 + h;
                float4 w0 = Ws4[k * (OC / 4) + ty * 2];
                float4 w1 = Ws4[k * (OC / 4) + ty * 2 + 1];
                unsigned long long w2[4];
                PACK2(w2[0], w0.x, w0.y);
                PACK2(w2[1], w0.z, w0.w);
                PACK2(w2[2], w1.x, w1.y);
                PACK2(w2[3], w1.z, w1.w);
                #pragma unroll
                for (int j = 0; j < 8; ++j) {
                    unsigned long long a2;
                    PACK2(a2, v[j + h], v[j + h]);
                    FMA2(acc[j][0], a2, w2[0]);
                    FMA2(acc[j][1], a2, w2[1]);
                    FMA2(acc[j][2], a2, w2[2]);
                    FMA2(acc[j][3], a2, w2[3]);
                }
            }
        }

        // ---- epilogue: add bias, store (contiguous 512B per t-row per warp) ----
        const int obase = och * OC + ty * 8;
        float4 b0 = __ldg((const float4*)&bias[obase]);
        float4 b1 = __ldg((const float4*)&bias[obase + 4]);
        #pragma unroll
        for (int j = 0; j < 8; ++j) {
            int t = t0 + 8 * tx + j;
            float r0, r1, r2, r3, r4, r5, r6, r7;
            UNPACK2(r0, r1, acc[j][0]);
            UNPACK2(r2, r3, acc[j][1]);
            UNPACK2(r4, r5, acc[j][2]);
            UNPACK2(r6, r7, acc[j][3]);
            float4 s0 = make_float4(r0 + b0.x, r1 + b0.y, r2 + b0.z, r3 + b0.w);
            float4 s1 = make_float4(r4 + b1.x, r5 + b1.y, r6 + b1.z, r7 + b1.w);
            float* po = out + ((size_t)bb * S_ + t) * O_ + obase;
            ((float4*)po)[0] = s0;
            ((float4*)po)[1] = s1;
        }
        __syncthreads();  // before overwriting Ws next chunk
    }
}

extern "C" void kernel_launch(void* const* d_in, const int* in_sizes, int n_in,
                              void* d_out, int out_size) {
    const float* x    = (const float*)d_in[0];  // (32, 2048, 7)
    const float* W    = (const float*)d_in[1];  // (512, 56, 3)
    const float* bias = (const float*)d_in[2];  // (512,)
    float* out = (float*)d_out;                 // (32, 2048, 512)

    const int smem_bytes = (KI * ZSTR + KK * OC) * (int)sizeof(float); // 115584
    cudaFuncSetAttribute(conv_main_kernel,
                         cudaFuncAttributeMaxDynamicSharedMemorySize, smem_bytes);

    wt_transpose_kernel<<<(KK * O_ + 255) / 256, 256>>>(W);

    dim3 grid(S_ / TT, B_);  // (16, 32) = 512 CTAs
    conv_main_kernel<<<grid, NTHREADS, smem_bytes>>>(x, bias, out);
}

// round 3
// speedup vs baseline: 1.1593x; 1.1593x over previous
#include <cuda_runtime.h>
#include <cstdint>
#include <cstddef>

// Problem constants
#define B_    32
#define S_    2048
#define C_    7
#define O_    512
#define KI    56      // 56 input features (c*8+m)
#define KH    3       // conv taps
#define KK    168     // KI*KH
#define TAO_  24
#define MT    168     // M*TAO zero-pad region
// Tiling
#define TT    128     // t per CTA tile
#define OC    64      // o per CTA (8 o-chunks)
#define NOCH  (O_/OC) // 8
#define ZSTR  132     // zs row stride (floats)
#define NTHREADS 128
#define NSLOT 37      // CTAs per o-chunk (37*8 = 296 = 2*148)
#define NTILE 512     // (b, t-tile) work units per o-chunk

// Transposed weights: g_Wt[k*512 + o] = W[o*168 + k]
__device__ float g_Wt[KK * O_];

__global__ void wt_transpose_kernel(const float* __restrict__ W) {
    int gid = blockIdx.x * blockDim.x + threadIdx.x;
    if (gid < KK * O_) {
        int k = gid >> 9;
        int o = gid & (O_ - 1);
        g_Wt[gid] = W[o * KK + k];
    }
}

#define PACK2(d, lo, hi)   asm("mov.b64 %0, {%1, %2};" : "=l"(d) : "f"(lo), "f"(hi))
#define UNPACK2(lo, hi, s) asm("mov.b64 {%0, %1}, %2;" : "=f"(lo), "=f"(hi) : "l"(s))
#define FMA2(acc, a, w)    asm("fma.rn.f32x2 %0, %1, %2, %0;" : "+l"(acc) : "l"(a), "l"(w))

__global__ __launch_bounds__(NTHREADS, 2)
void conv_main_kernel(const float* __restrict__ x,
                      const float* __restrict__ bias,
                      float* __restrict__ out) {
    extern __shared__ float smem[];
    float* zs = smem;                 // [KI][ZSTR]  29568 B
    float* Ws = smem + KI * ZSTR;     // [KK][OC]    43008 B   (total 72576 B)

    const int tid = threadIdx.x;
    const int ty  = tid & 7;    // 8 o-groups x 8 o = 64 o
    const int tx  = tid >> 3;   // 16 t-groups x 8 t = 128 t
    const int och  = blockIdx.x & 7;         // o-chunk, fixed per CTA
    const int slot = blockIdx.x >> 3;        // 0..36

    // ---- stage W chunk ONCE: Ws[k][0..63] = g_Wt[k][och*64 .. +63] ----
    {
        const float4* Wt4 = (const float4*)g_Wt;
        for (int idx = tid; idx < KK * (OC / 4); idx += NTHREADS) {
            int k = idx >> 4;          // /16
            int f = idx & 15;
            ((float4*)Ws)[idx] = __ldg(&Wt4[k * (O_ / 4) + och * (OC / 4) + f]);
        }
    }

    // per-thread bias (8 consecutive o)
    const int obase = och * OC + ty * 8;
    float4 b0 = __ldg((const float4*)&bias[obase]);
    float4 b1 = __ldg((const float4*)&bias[obase + 4]);

    const float4* zs4 = (const float4*)zs;

    for (int tile = slot; tile < NTILE; tile += NSLOT) {
        const int bb = tile >> 4;
        const int t0 = (tile & 15) * TT;
        const float* xb = x + (size_t)bb * S_ * C_;

        __syncthreads();   // prior compute done reading zs (covers Ws stage on iter 0)

        // ---- stage z tile: zs[i][tt] = z[bb, i, t0-1+tt], tt in [0,130) ----
        for (int idx = tid; idx < KI * (TT + 2); idx += NTHREADS) {
            int i  = idx / (TT + 2);
            int tt = idx - i * (TT + 2);
            int c  = i >> 3;
            int m  = i & 7;
            int s  = t0 - 1 + tt;
            int sm = s & (S_ - 1);          // wrap (handles s=-1 and s=2048)
            float v = 0.0f;
            if (sm >= MT) v = __ldg(&xb[(sm - TAO_ * m) * C_ + c]);
            zs[i * ZSTR + tt] = v;
        }
        __syncthreads();

        // ---- compute: 8t x 8o per thread, f32x2 packed accumulators ----
        unsigned long long acc[8][4];
        #pragma unroll
        for (int j = 0; j < 8; ++j) {
            #pragma unroll
            for (int p = 0; p < 4; ++p) acc[j][p] = 0ULL;
        }

        const int zbase = 2 * tx;  // float4 index within zs row
        #pragma unroll 1
        for (int i = 0; i < KI; ++i) {
            float4 va = zs4[i * (ZSTR / 4) + zbase];
            float4 vb = zs4[i * (ZSTR / 4) + zbase + 1];
            float4 vc = zs4[i * (ZSTR / 4) + zbase + 2];
            float v[10] = { va.x, va.y, va.z, va.w,
                            vb.x, vb.y, vb.z, vb.w,
                            vc.x, vc.y };
            // duplicate-packs hoisted out of the h loop: 10 movs per i
            unsigned long long dup[10];
            #pragma unroll
            for (int q = 0; q < 10; ++q) PACK2(dup[q], v[q], v[q]);

            #pragma unroll
            for (int h = 0; h < KH; ++h) {
                int k = i * 3 + h;
                // W pairs loaded directly as 64-bit halves — zero pack movs
                const ulonglong2* pw =
                    (const ulonglong2*)&Ws[k * OC + ty * 8];
                ulonglong2 wA = pw[0];
                ulonglong2 wB = pw[1];
                #pragma unroll
                for (int j = 0; j < 8; ++j) {
                    FMA2(acc[j][0], dup[j + h], wA.x);
                    FMA2(acc[j][1], dup[j + h], wA.y);
                    FMA2(acc[j][2], dup[j + h], wB.x);
                    FMA2(acc[j][3], dup[j + h], wB.y);
                }
            }
        }

        // ---- epilogue: add bias, store ----
        #pragma unroll
        for (int j = 0; j < 8; ++j) {
            int t = t0 + 8 * tx + j;
            float r0, r1, r2, r3, r4, r5, r6, r7;
            UNPACK2(r0, r1, acc[j][0]);
            UNPACK2(r2, r3, acc[j][1]);
            UNPACK2(r4, r5, acc[j][2]);
            UNPACK2(r6, r7, acc[j][3]);
            float4 s0 = make_float4(r0 + b0.x, r1 + b0.y, r2 + b0.z, r3 + b0.w);
            float4 s1 = make_float4(r4 + b1.x, r5 + b1.y, r6 + b1.z, r7 + b1.w);
            float* po = out + ((size_t)bb * S_ + t) * O_ + obase;
            ((float4*)po)[0] = s0;
            ((float4*)po)[1] = s1;
        }
    }
}

extern "C" void kernel_launch(void* const* d_in, const int* in_sizes, int n_in,
                              void* d_out, int out_size) {
    const float* x    = (const float*)d_in[0];  // (32, 2048, 7)
    const float* W    = (const float*)d_in[1];  // (512, 56, 3)
    const float* bias = (const float*)d_in[2];  // (512,)
    float* out = (float*)d_out;                 // (32, 2048, 512)

    const int smem_bytes = (KI * ZSTR + KK * OC) * (int)sizeof(float); // 72576
    cudaFuncSetAttribute(conv_main_kernel,
                         cudaFuncAttributeMaxDynamicSharedMemorySize, smem_bytes);

    wt_transpose_kernel<<<(KK * O_ + 255) / 256, 256>>>(W);

    conv_main_kernel<<<NSLOT * NOCH, NTHREADS, smem_bytes>>>(x, bias, out);
}

// round 4
// speedup vs baseline: 1.2679x; 1.0937x over previous
#include <cuda_runtime.h>
#include <cstdint>
#include <cstddef>

// Problem constants
#define B_    32
#define S_    2048
#define C_    7
#define O_    512
#define KI    56      // 56 input features (c*8+m)
#define KH    3       // conv taps
#define KK    168     // KI*KH
#define TAO_  24
#define MT    168     // M*TAO zero-pad region
// Tiling
#define TT    128     // t per CTA tile
#define OC    64      // o per CTA (8 o-chunks)
#define NOCH  (O_/OC) // 8
#define ZSTR  132     // zs row stride (floats)
#define NTHREADS 128
#define NSLOT 37      // CTAs per o-chunk (37*8 = 296 = 2*148)
#define NTILE 512     // (b, t-tile) work units per o-chunk
#define ZELEMS (KI*(TT+2))   // 7280

// Transposed weights: g_Wt[k*512 + o] = W[o*168 + k]
__device__ float g_Wt[KK * O_];

__global__ void wt_transpose_kernel(const float* __restrict__ W) {
    int gid = blockIdx.x * blockDim.x + threadIdx.x;
    if (gid < KK * O_) {
        int k = gid >> 9;
        int o = gid & (O_ - 1);
        g_Wt[gid] = W[o * KK + k];
    }
}

#define PACK2(d, lo, hi)   asm("mov.b64 %0, {%1, %2};" : "=l"(d) : "f"(lo), "f"(hi))
#define UNPACK2(lo, hi, s) asm("mov.b64 {%0, %1}, %2;" : "=f"(lo), "=f"(hi) : "l"(s))
#define FMA2(acc, a, w)    asm("fma.rn.f32x2 %0, %1, %2, %0;" : "+l"(acc) : "l"(a), "l"(w))
#define CP_COMMIT()        asm volatile("cp.async.commit_group;")
#define CP_WAIT1()         asm volatile("cp.async.wait_group 1;")

// Async-gather one z tile into zsbuf: zs[i][tt] = z[bb, i, t0-1+tt], tt in [0,130)
__device__ __forceinline__ void stage_async(float* zsbuf, const float* xb,
                                            int t0, int tid) {
    uint32_t sbase = (uint32_t)__cvta_generic_to_shared(zsbuf);
    int i = 0, tt = tid;            // tid < 128 < 130, so first element is row 0
    for (int e = tid; e < ZELEMS; e += NTHREADS) {
        int c  = i >> 3;
        int m  = i & 7;
        int s  = t0 - 1 + tt;
        int sm = s & (S_ - 1);                      // wrap handles -1 and 2048
        int valid = (sm >= MT) ? 4 : 0;
        const float* g = xb + (sm - TAO_ * m) * C_ + c;
        if (!valid) g = xb;                         // safe address when zfilling
        uint32_t d = sbase + (uint32_t)(i * ZSTR + tt) * 4u;
        asm volatile("cp.async.ca.shared.global [%0], [%1], 4, %2;"
                     :: "r"(d), "l"(g), "r"(valid));
        tt += NTHREADS;
        if (tt >= TT + 2) { tt -= (TT + 2); ++i; }
    }
}

__global__ __launch_bounds__(NTHREADS, 2)
void conv_main_kernel(const float* __restrict__ x,
                      const float* __restrict__ bias,
                      float* __restrict__ out) {
    extern __shared__ float smem[];
    float* zsb[2] = { smem, smem + KI * ZSTR };       // 2 x 29568 B
    float* Ws = smem + 2 * KI * ZSTR;                 // [KK][OC] 43008 B (tot 102144)

    const int tid = threadIdx.x;
    const int ty  = tid & 7;    // 8 o-groups x 8 o = 64 o
    const int tx  = tid >> 3;   // 16 t-groups x 8 t = 128 t
    const int och  = blockIdx.x & 7;     // o-chunk, fixed per CTA
    const int slot = blockIdx.x >> 3;    // 0..36

    // ---- stage W chunk ONCE: Ws[k][0..63] = g_Wt[k][och*64 .. +63] ----
    {
        const float4* Wt4 = (const float4*)g_Wt;
        for (int idx = tid; idx < KK * (OC / 4); idx += NTHREADS) {
            int k = idx >> 4;
            int f = idx & 15;
            ((float4*)Ws)[idx] = __ldg(&Wt4[k * (O_ / 4) + och * (OC / 4) + f]);
        }
    }

    const int obase = och * OC + ty * 8;
    float4 b0 = __ldg((const float4*)&bias[obase]);
    float4 b1 = __ldg((const float4*)&bias[obase + 4]);

    // ---- prime the async pipeline: prefetch first two tiles ----
    {
        int tile0 = slot;
        if (tile0 < NTILE)
            stage_async(zsb[0], x + (size_t)(tile0 >> 4) * S_ * C_,
                        (tile0 & 15) * TT, tid);
        CP_COMMIT();
        int tile1 = slot + NSLOT;
        if (tile1 < NTILE)
            stage_async(zsb[1], x + (size_t)(tile1 >> 4) * S_ * C_,
                        (tile1 & 15) * TT, tid);
        CP_COMMIT();
    }

    int buf = 0;
    for (int tile = slot; tile < NTILE; tile += NSLOT, buf ^= 1) {
        const int bb = tile >> 4;
        const int t0 = (tile & 15) * TT;

        CP_WAIT1();          // this buf's gather done (only next's may be pending)
        __syncthreads();     // visible to all warps (also covers Ws stage, iter 0)

        const float4* zs4 = (const float4*)zsb[buf];

        // ---- compute: 8t x 8o per thread, f32x2 packed accumulators ----
        unsigned long long acc[8][4];
        #pragma unroll
        for (int j = 0; j < 8; ++j) {
            #pragma unroll
            for (int p = 0; p < 4; ++p) acc[j][p] = 0ULL;
        }

        const int zbase = 2 * tx;
        #pragma unroll 2
        for (int i = 0; i < KI; ++i) {
            float4 va = zs4[i * (ZSTR / 4) + zbase];
            float4 vb = zs4[i * (ZSTR / 4) + zbase + 1];
            float4 vc = zs4[i * (ZSTR / 4) + zbase + 2];
            float v[10] = { va.x, va.y, va.z, va.w,
                            vb.x, vb.y, vb.z, vb.w,
                            vc.x, vc.y };
            unsigned long long dup[10];
            #pragma unroll
            for (int q = 0; q < 10; ++q) PACK2(dup[q], v[q], v[q]);

            #pragma unroll
            for (int h = 0; h < KH; ++h) {
                int k = i * 3 + h;
                const ulonglong2* pw = (const ulonglong2*)&Ws[k * OC + ty * 8];
                ulonglong2 wA = pw[0];
                ulonglong2 wB = pw[1];
                #pragma unroll
                for (int j = 0; j < 8; ++j) {
                    FMA2(acc[j][0], dup[j + h], wA.x);
                    FMA2(acc[j][1], dup[j + h], wA.y);
                    FMA2(acc[j][2], dup[j + h], wB.x);
                    FMA2(acc[j][3], dup[j + h], wB.y);
                }
            }
        }

        // ---- epilogue: add bias, store ----
        #pragma unroll
        for (int j = 0; j < 8; ++j) {
            int t = t0 + 8 * tx + j;
            float r0, r1, r2, r3, r4, r5, r6, r7;
            UNPACK2(r0, r1, acc[j][0]);
            UNPACK2(r2, r3, acc[j][1]);
            UNPACK2(r4, r5, acc[j][2]);
            UNPACK2(r6, r7, acc[j][3]);
            float4 s0 = make_float4(r0 + b0.x, r1 + b0.y, r2 + b0.z, r3 + b0.w);
            float4 s1 = make_float4(r4 + b1.x, r5 + b1.y, r6 + b1.z, r7 + b1.w);
            float* po = out + ((size_t)bb * S_ + t) * O_ + obase;
            ((float4*)po)[0] = s0;
            ((float4*)po)[1] = s1;
        }

        __syncthreads();     // everyone done reading zsb[buf] before refilling it

        int pf = tile + 2 * NSLOT;
        if (pf < NTILE)
            stage_async(zsb[buf], x + (size_t)(pf >> 4) * S_ * C_,
                        (pf & 15) * TT, tid);
        CP_COMMIT();         // commit every iteration (possibly empty) to keep counts uniform
    }
}

extern "C" void kernel_launch(void* const* d_in, const int* in_sizes, int n_in,
                              void* d_out, int out_size) {
    const float* x    = (const float*)d_in[0];  // (32, 2048, 7)
    const float* W    = (const float*)d_in[1];  // (512, 56, 3)
    const float* bias = (const float*)d_in[2];  // (512,)
    float* out = (float*)d_out;                 // (32, 2048, 512)

    const int smem_bytes = (2 * KI * ZSTR + KK * OC) * (int)sizeof(float); // 102144
    cudaFuncSetAttribute(conv_main_kernel,
                         cudaFuncAttributeMaxDynamicSharedMemorySize, smem_bytes);

    wt_transpose_kernel<<<(KK * O_ + 255) / 256, 256>>>(W);

    conv_main_kernel<<<NSLOT * NOCH, NTHREADS, smem_bytes>>>(x, bias, out);
}

// round 5
// speedup vs baseline: 1.3150x; 1.0371x over previous
#include <cuda_runtime.h>
#include <cstdint>
#include <cstddef>

// Problem constants
#define B_    32
#define S_    2048
#define C_    7
#define O_    512
#define KI    56
#define KH    3
#define KK    168
#define TAO_  24
#define MT    168
#define XFLAT (S_*C_)        // 14336
// Tiling
#define TT    256            // t per tile
#define OC    64             // o per CTA
#define NOCH  (O_/OC)        // 8
#define ZSTR  260            // zs row stride (floats), /4 = 65
#define XROWS 428            // staged x rows per tile
#define XS_N  (XROWS*C_)     // 2996 floats
#define NTHREADS 128
#define NSLOT 37             // 37*8 = 296 = 2*148 CTAs
#define NTILE 256            // 32 b * 8 t-tiles

__device__ float g_Wt[KK * O_];   // g_Wt[k*512+o] = W[o*168+k]

__global__ void wt_transpose_kernel(const float* __restrict__ W) {
    int gid = blockIdx.x * blockDim.x + threadIdx.x;
    if (gid < KK * O_) {
        int k = gid >> 9;
        int o = gid & (O_ - 1);
        g_Wt[gid] = W[o * KK + k];
    }
}

#define PACK2(d, lo, hi)   asm("mov.b64 %0, {%1, %2};" : "=l"(d) : "f"(lo), "f"(hi))
#define UNPACK2(lo, hi, s) asm("mov.b64 {%0, %1}, %2;" : "=f"(lo), "=f"(hi) : "l"(s))
#define FMA2(acc, a, w)    asm("fma.rn.f32x2 %0, %1, %2, %0;" : "+l"(acc) : "l"(a), "l"(w))
#define CP_COMMIT()        asm volatile("cp.async.commit_group;")
#define CP_WAIT0()         asm volatile("cp.async.wait_group 0;")

// Coalesced stage of raw x rows: xs[f] = xb[(g0+f) mod 14336], f in [0, 2996)
__device__ __forceinline__ void stage_xs(float* xs, const float* xb,
                                         int t0, int tid) {
    uint32_t sb = (uint32_t)__cvta_generic_to_shared(xs);
    int g0 = ((t0 - (MT + 1)) & (S_ - 1)) * C_;
    #pragma unroll 4
    for (int f = tid; f < XS_N; f += NTHREADS) {
        int g = g0 + f;
        if (g >= XFLAT) g -= XFLAT;
        asm volatile("cp.async.ca.shared.global [%0], [%1], 4;"
                     :: "r"(sb + (uint32_t)f * 4u), "l"(xb + g));
    }
}

__global__ __launch_bounds__(NTHREADS, 2)
void conv_main_kernel(const float* __restrict__ x,
                      const float* __restrict__ bias,
                      float* __restrict__ out) {
    extern __shared__ float smem[];
    float* zs = smem;                       // 56*260      = 14560 floats
    float* Ws = smem + KI * ZSTR;           // 168*64      = 10752
    float* xs = Ws + KK * OC;               // 3008 (2996 used)

    const int tid = threadIdx.x;
    const int ty  = tid & 7;     // 8 o-groups x 8 o
    const int tx  = tid >> 3;    // 16 t-groups x 16 t = 256 t
    const int och  = blockIdx.x & 7;
    const int slot = blockIdx.x >> 3;

    // prologue: prefetch xs for first tile, stage Ws
    stage_xs(xs, x + (size_t)(slot >> 3) * XFLAT, (slot & 7) * TT, tid);
    CP_COMMIT();
    {
        const float4* Wt4 = (const float4*)g_Wt;
        for (int idx = tid; idx < KK * (OC / 4); idx += NTHREADS) {
            int k = idx >> 4;
            int f = idx & 15;
            ((float4*)Ws)[idx] = __ldg(&Wt4[k * (O_ / 4) + och * (OC / 4) + f]);
        }
    }
    const int obase = och * OC + ty * 8;
    float4 b0 = __ldg((const float4*)&bias[obase]);
    float4 b1 = __ldg((const float4*)&bias[obase + 4]);

    for (int tile = slot; tile < NTILE; tile += NSLOT) {
        const int bb = tile >> 3;
        const int t0 = (tile & 7) * TT;

        CP_WAIT0();          // xs for this tile resident
        __syncthreads();     // + all warps done with zs from previous tile

        // ---- transpose xs -> zs : zs[i][tt] = (sm>=168)? xs[(tt+168-24m)*7+c] : 0
        {
            int i = 0, tt4 = tid;
            while (tt4 >= (ZSTR / 4)) { tt4 -= (ZSTR / 4); ++i; }
            for (int e = tid; e < KI * (ZSTR / 4); e += NTHREADS) {
                int m = i & 7, c = i >> 3;
                int btt = tt4 * 4;
                int q0  = btt + MT - TAO_ * m;
                int s0  = t0 - 1 + btt;
                float vk[4];
                #pragma unroll
                for (int k = 0; k < 4; ++k) {
                    int sm = (s0 + k) & (S_ - 1);
                    vk[k] = (sm >= MT) ? xs[(q0 + k) * C_ + c] : 0.0f;
                }
                *(float4*)&zs[i * ZSTR + btt] =
                    make_float4(vk[0], vk[1], vk[2], vk[3]);
                tt4 += NTHREADS;
                while (tt4 >= (ZSTR / 4)) { tt4 -= (ZSTR / 4); ++i; }
            }
        }
        __syncthreads();     // zs ready; xs fully consumed

        // prefetch xs for next tile (lands during compute)
        int nxt = tile + NSLOT;
        if (nxt < NTILE)
            stage_xs(xs, x + (size_t)(nxt >> 3) * XFLAT, (nxt & 7) * TT, tid);
        CP_COMMIT();

        // ---- compute: 16t x 8o per thread ----
        unsigned long long acc[16][4];
        #pragma unroll
        for (int j = 0; j < 16; ++j) {
            #pragma unroll
            for (int p = 0; p < 4; ++p) acc[j][p] = 0ULL;
        }

        const float4* zs4 = (const float4*)zs;
        const int zbase = 4 * tx;
        #pragma unroll 1
        for (int i = 0; i < KI; ++i) {
            float4 A = zs4[i * (ZSTR / 4) + zbase];
            float4 Bv = zs4[i * (ZSTR / 4) + zbase + 1];
            float4 Cv = zs4[i * (ZSTR / 4) + zbase + 2];
            float4 D = zs4[i * (ZSTR / 4) + zbase + 3];
            float4 E = zs4[i * (ZSTR / 4) + zbase + 4];
            float v[18] = { A.x, A.y, A.z, A.w,  Bv.x, Bv.y, Bv.z, Bv.w,
                            Cv.x, Cv.y, Cv.z, Cv.w,  D.x, D.y, D.z, D.w,
                            E.x, E.y };
            unsigned long long dup[18];
            #pragma unroll
            for (int q = 0; q < 18; ++q) PACK2(dup[q], v[q], v[q]);

            #pragma unroll
            for (int h = 0; h < KH; ++h) {
                const ulonglong2* pw =
                    (const ulonglong2*)&Ws[(i * 3 + h) * OC + ty * 8];
                ulonglong2 wA = pw[0];
                ulonglong2 wB = pw[1];
                #pragma unroll
                for (int j = 0; j < 16; ++j) {
                    FMA2(acc[j][0], dup[j + h], wA.x);
                    FMA2(acc[j][1], dup[j + h], wA.y);
                    FMA2(acc[j][2], dup[j + h], wB.x);
                    FMA2(acc[j][3], dup[j + h], wB.y);
                }
            }
        }

        // ---- epilogue ----
        #pragma unroll
        for (int j = 0; j < 16; ++j) {
            int t = t0 + 16 * tx + j;
            float r0, r1, r2, r3, r4, r5, r6, r7;
            UNPACK2(r0, r1, acc[j][0]);
            UNPACK2(r2, r3, acc[j][1]);
            UNPACK2(r4, r5, acc[j][2]);
            UNPACK2(r6, r7, acc[j][3]);
            float4 s0 = make_float4(r0 + b0.x, r1 + b0.y, r2 + b0.z, r3 + b0.w);
            float4 s1 = make_float4(r4 + b1.x, r5 + b1.y, r6 + b1.z, r7 + b1.w);
            float* po = out + ((size_t)bb * S_ + t) * O_ + obase;
            ((float4*)po)[0] = s0;
            ((float4*)po)[1] = s1;
        }
        // loop-top sync protects zs before next transpose
    }
}

extern "C" void kernel_launch(void* const* d_in, const int* in_sizes, int n_in,
                              void* d_out, int out_size) {
    const float* x    = (const float*)d_in[0];  // (32, 2048, 7)
    const float* W    = (const float*)d_in[1];  // (512, 56, 3)
    const float* bias = (const float*)d_in[2];  // (512,)
    float* out = (float*)d_out;                 // (32, 2048, 512)

    const int smem_bytes = (KI * ZSTR + KK * OC + 3008) * (int)sizeof(float); // 113280
    cudaFuncSetAttribute(conv_main_kernel,
                         cudaFuncAttributeMaxDynamicSharedMemorySize, smem_bytes);

    wt_transpose_kernel<<<(KK * O_ + 255) / 256, 256>>>(W);

    conv_main_kernel<<<NSLOT * NOCH, NTHREADS, smem_bytes>>>(x, bias, out);
}

// round 7
// speedup vs baseline: 1.7855x; 1.3578x over previous
#include <cuda_runtime.h>
#include <cuda_bf16.h>
#include <cstdint>
#include <cstddef>

// ---------------- problem constants ----------------
#define B_    32
#define S_    2048
#define C_    7
#define O_    512
#define KLOG  168          // real K, k = i*3+h, i = c*8+m
#define KP    176          // padded K (11 ksteps of 16)
#define NKS   11
#define TT    128          // t per tile (M)
#define OCH   128          // o per chunk (N)
#define NCHUNK 4
#define NSLOT 37           // 37*4 = 148 persistent CTAs
#define NTILE 512          // t-tiles per chunk (32 b * 16)
#define NTH   256

#define KSTR  184          // bf16 row stride for zs/Ws (368B = 16B*23, 92 words)
#define ROWB  368

#define XSROWS 298
#define XSN   (XSROWS*C_)  // 2086 floats

// ---------------- smem byte layout ----------------
#define SM_BIAS  0                      // 128 f  (512B)
#define SM_KOFF  512                    // 176 int (704B)
#define SM_KH    1216                   // 176 int (704B)
#define SM_XS0   1920                   // 8344B
#define SM_XS1   10272                  // 8344B
#define SM_ZHI   18624                  // 128*368 = 47104
#define SM_ZLO   65728
#define SM_WHI   112832
#define SM_WLO   159936
#define SM_TOTAL 207040

// W pre-split: [hi|lo][o=512][k=176] bf16
__device__ __nv_bfloat16 g_Wb[2 * 512 * KP];

__global__ void wsetup_kernel(const float* __restrict__ W) {
    int gid = blockIdx.x * blockDim.x + threadIdx.x;
    if (gid >= 512 * KP) return;
    int o = gid / KP, k = gid % KP;
    float w = (k < KLOG) ? W[o * KLOG + k] : 0.f;
    __nv_bfloat16 hi = __float2bfloat16(w);
    __nv_bfloat16 lo = __float2bfloat16(w - __bfloat162float(hi));
    g_Wb[gid] = hi;
    g_Wb[512 * KP + gid] = lo;
}

// ---------------- PTX helpers ----------------
#define CP_COMMIT()  asm volatile("cp.async.commit_group;")
#define CP_WAIT0()   asm volatile("cp.async.wait_group 0;")

#define LDSM4(r, addr) \
    asm volatile("ldmatrix.sync.aligned.m8n8.x4.shared.b16 {%0,%1,%2,%3}, [%4];" \
        : "=r"((r)[0]), "=r"((r)[1]), "=r"((r)[2]), "=r"((r)[3]) : "r"(addr))

#define MMA16816(d, a, b0, b1) \
    asm volatile("mma.sync.aligned.m16n8k16.row.col.f32.bf16.bf16.f32 " \
        "{%0,%1,%2,%3},{%4,%5,%6,%7},{%8,%9},{%0,%1,%2,%3};" \
        : "+f"((d)[0]), "+f"((d)[1]), "+f"((d)[2]), "+f"((d)[3]) \
        : "r"((a)[0]), "r"((a)[1]), "r"((a)[2]), "r"((a)[3]), "r"(b0), "r"(b1))

// coalesced modular stage of raw x rows covering one t-tile
__device__ __forceinline__ void stage_xs(uint32_t sdst, const float* xb, int t0) {
    int g0 = ((t0 - 169) & (S_ - 1)) * C_;
    for (int f = threadIdx.x; f < XSN; f += NTH) {
        int g = g0 + f;
        if (g >= S_ * C_) g -= S_ * C_;
        asm volatile("cp.async.ca.shared.global [%0], [%1], 4;"
                     :: "r"(sdst + (uint32_t)f * 4u), "l"(xb + g));
    }
}

__global__ __launch_bounds__(NTH, 1)
void conv_hmma_kernel(const float* __restrict__ x,
                      const float* __restrict__ bias,
                      float* __restrict__ out) {
    extern __shared__ char smem[];
    const uint32_t sb = (uint32_t)__cvta_generic_to_shared(smem);
    const int tid  = threadIdx.x;
    const int lane = tid & 31;
    const int wid  = tid >> 5;
    const int chunk = blockIdx.x & 3;
    const int slot  = blockIdx.x >> 2;
    const int ntiles = (NTILE - slot + NSLOT - 1) / NSLOT;

    float* biasS = (float*)(smem + SM_BIAS);
    int*   koffS = (int*)(smem + SM_KOFF);
    int*   khS   = (int*)(smem + SM_KH);

    for (int j = tid; j < OCH; j += NTH) biasS[j] = bias[chunk * OCH + j];
    for (int k = tid; k < KP; k += NTH) {
        int i = k / 3, h = k - 3 * i, m = i & 7, c = i >> 3;
        koffS[k] = (k < KLOG) ? ((h + KLOG - 24 * m) * C_ + c) : 0;
        khS[k]   = (k < KLOG) ? h : 3;       // sentinel -> always zero
    }

    // stage W (hi+lo) slice for this chunk: 2 x 128 rows x 22 x 16B
    {
        const char* wsrc = (const char*)g_Wb;
        for (int f = tid; f < 2 * 128 * 22; f += NTH) {
            int half = f / (128 * 22);
            int rem  = f - half * (128 * 22);
            int n = rem / 22, seg = rem - n * 22;
            const char* src = wsrc + (size_t)(half * 512 + chunk * OCH + n) * (KP * 2) + seg * 16;
            uint32_t dst = sb + (half ? SM_WLO : SM_WHI) + (uint32_t)n * ROWB + seg * 16;
            asm volatile("cp.async.cg.shared.global [%0], [%1], 16;"
                         :: "r"(dst), "l"(src));
        }
    }
    // stage xs for tile 0
    {
        int tl = slot;
        stage_xs(sb + SM_XS0, x + (size_t)(tl >> 4) * S_ * C_, (tl & 15) << 7);
    }
    CP_COMMIT();

    // per-lane ldmatrix base offsets
    const int warp_m = (wid & 3) * 32;
    const int warp_n = (wid >> 2) * 64;
    const int jT = lane >> 3;           // tile index within x4
    // A x4: tiles [m0,k0],[m0+8,k0],[m0,k0+8],[m0+8,k0+8]
    const uint32_t aOff = (uint32_t)(warp_m + ((jT & 1) << 3) + (lane & 7)) * ROWB
                        + (uint32_t)((jT >> 1) << 4);
    // B x4 #p covers ntiles 2p,2p+1: tiles [n0,k0],[n0,k0+8],[n0+8,k0],[n0+8,k0+8]
    uint32_t bOff[4];
    #pragma unroll
    for (int p = 0; p < 4; ++p)
        bOff[p] = (uint32_t)(warp_n + p * 16 + ((jT >> 1) << 3) + (lane & 7)) * ROWB
                + (uint32_t)((jT & 1) << 4);

    const int g  = lane >> 2;           // 0..7
    const int c2 = (lane & 3) * 2;      // 0,2,4,6
    uint32_t* zw = (uint32_t*)smem;     // word view of smem

    for (int n = 0; n < ntiles; ++n) {
        const int tl = slot + n * NSLOT;
        const int bb = tl >> 4;
        const int t0 = (tl & 15) << 7;

        CP_WAIT0();
        __syncthreads();                // xs[cur] ready; zs free (prev mma done)

        // prefetch xs for next tile into the other buffer
        if (n + 1 < ntiles) {
            int tl1 = slot + (n + 1) * NSLOT;
            stage_xs(((n + 1) & 1) ? (sb + SM_XS1) : (sb + SM_XS0),
                     x + (size_t)(tl1 >> 4) * S_ * C_, (tl1 & 15) << 7);
        }
        CP_COMMIT();

        // ---- build zs_hi / zs_lo: warp w owns rows w*16..w*16+15 ----
        {
            const float* xs = (const float*)(smem + ((n & 1) ? SM_XS1 : SM_XS0));
            for (int rr = 0; rr < 16; ++rr) {
                int r = wid * 16 + rr;
                int s = t0 + r - 1;
                uint32_t vm = 0;
                if (((s)     & (S_-1)) >= KLOG) vm |= 1;
                if (((s + 1) & (S_-1)) >= KLOG) vm |= 2;
                if (((s + 2) & (S_-1)) >= KLOG) vm |= 4;
                const float* xr = xs + r * C_;
                uint32_t* zH = zw + (SM_ZHI >> 2) + r * (ROWB >> 2);
                uint32_t* zL = zw + (SM_ZLO >> 2) + r * (ROWB >> 2);
                #pragma unroll
                for (int qs = 0; qs < 3; ++qs) {
                    int q = lane + qs * 32;
                    if (q < KP / 2) {
                        int k = 2 * q;
                        float f0 = ((vm >> khS[k])   & 1) ? xr[koffS[k]]   : 0.f;
                        float f1 = ((vm >> khS[k+1]) & 1) ? xr[koffS[k+1]] : 0.f;
                        __nv_bfloat16 h0 = __float2bfloat16(f0);
                        __nv_bfloat16 h1 = __float2bfloat16(f1);
                        __nv_bfloat16 l0 = __float2bfloat16(f0 - __bfloat162float(h0));
                        __nv_bfloat16 l1 = __float2bfloat16(f1 - __bfloat162float(h1));
                        zH[q] = (uint32_t)__bfloat16_as_ushort(h0)
                              | ((uint32_t)__bfloat16_as_ushort(h1) << 16);
                        zL[q] = (uint32_t)__bfloat16_as_ushort(l0)
                              | ((uint32_t)__bfloat16_as_ushort(l1) << 16);
                    }
                }
            }
        }
        __syncthreads();                // zs visible to all warps

        // ---- mma: 3 passes x 11 ksteps; warp tile 32m x 64n ----
        float acc[2][8][4];
        #pragma unroll
        for (int mt = 0; mt < 2; ++mt)
            #pragma unroll
            for (int nt = 0; nt < 8; ++nt)
                #pragma unroll
                for (int q = 0; q < 4; ++q) acc[mt][nt][q] = 0.f;

        const uint32_t zB[3] = { SM_ZHI, SM_ZLO, SM_ZHI };
        const uint32_t wB[3] = { SM_WHI, SM_WHI, SM_WLO };
        #pragma unroll 1
        for (int ps = 0; ps < 3; ++ps) {
            uint32_t aBase = sb + zB[ps] + aOff;
            uint32_t bBase = sb + wB[ps];
            #pragma unroll 1
            for (int ks = 0; ks < NKS; ++ks) {
                uint32_t kb = (uint32_t)ks * 32u;
                uint32_t A0[4], A1[4], Bf[4][4];
                LDSM4(A0, aBase + kb);
                LDSM4(A1, aBase + 16 * ROWB + kb);
                #pragma unroll
                for (int p = 0; p < 4; ++p)
                    LDSM4(Bf[p], bBase + bOff[p] + kb);
                #pragma unroll
                for (int nt = 0; nt < 8; ++nt) {
                    uint32_t b0 = Bf[nt >> 1][(nt & 1) << 1];
                    uint32_t b1 = Bf[nt >> 1][((nt & 1) << 1) + 1];
                    MMA16816(acc[0][nt], A0, b0, b1);
                    MMA16816(acc[1][nt], A1, b0, b1);
                }
            }
        }

        // ---- epilogue: bias + store ----
        #pragma unroll
        for (int mt = 0; mt < 2; ++mt) {
            size_t row = (size_t)bb * S_ + t0 + warp_m + mt * 16 + g;
            #pragma unroll
            for (int nt = 0; nt < 8; ++nt) {
                int ncol = warp_n + nt * 8 + c2;
                float bi0 = biasS[ncol], bi1 = biasS[ncol + 1];
                float* p0 = out + row * O_ + chunk * OCH + ncol;
                *(float2*)p0 = make_float2(acc[mt][nt][0] + bi0,
                                           acc[mt][nt][1] + bi1);
                *(float2*)(p0 + 8 * O_) = make_float2(acc[mt][nt][2] + bi0,
                                                      acc[mt][nt][3] + bi1);
            }
        }
    }
}

extern "C" void kernel_launch(void* const* d_in, const int* in_sizes, int n_in,
                              void* d_out, int out_size) {
    const float* x    = (const float*)d_in[0];  // (32, 2048, 7)
    const float* W    = (const float*)d_in[1];  // (512, 56, 3)
    const float* bias = (const float*)d_in[2];  // (512,)
    float* out = (float*)d_out;                 // (32, 2048, 512)

    cudaFuncSetAttribute(conv_hmma_kernel,
                         cudaFuncAttributeMaxDynamicSharedMemorySize, SM_TOTAL);

    wsetup_kernel<<<(512 * KP + 255) / 256, 256>>>(W);
    conv_hmma_kernel<<<NSLOT * NCHUNK, NTH, SM_TOTAL>>>(x, bias, out);
}

// round 8
// speedup vs baseline: 1.8007x; 1.0085x over previous
#include <cuda_runtime.h>
#include <cuda_bf16.h>
#include <cstdint>
#include <cstddef>

// ---------------- problem constants ----------------
#define B_    32
#define S_    2048
#define C_    7
#define O_    512
#define KLOG  168          // real K, k = i*3+h, i = c*8+m
#define KP    176          // padded K (11 ksteps of 16)
#define NKS   11
#define TT    128          // t per tile (M)
#define OCH   128          // o per chunk (N)
#define NCHUNK 4
#define NSLOT 37           // 37*4 = 148 persistent CTAs
#define NTILE 512          // t-tiles per chunk (32 b * 16)
#define NTH   256

#define ROWB  368          // bf16 row stride in bytes (184 bf16)

#define XSROWS 298
#define XSN   (XSROWS*C_)  // 2086 floats

// ---------------- smem byte layout ----------------
#define SM_BIAS  0                      // 128 f  (512B)
#define SM_KOFF  512                    // 176 int (704B)
#define SM_KH    1216                   // 176 int (704B)
#define SM_XS0   1920                   // 8344B
#define SM_XS1   10272                  // 8344B
#define SM_ZHI   18624                  // 128*368 = 47104
#define SM_ZLO   65728
#define SM_WHI   112832
#define SM_WLO   159936
#define SM_TOTAL 207040

// W pre-split: [hi|lo][o=512][k=176] bf16
__device__ __nv_bfloat16 g_Wb[2 * 512 * KP];

__global__ void wsetup_kernel(const float* __restrict__ W) {
    int gid = blockIdx.x * blockDim.x + threadIdx.x;
    if (gid >= 512 * KP) return;
    int o = gid / KP, k = gid % KP;
    float w = (k < KLOG) ? W[o * KLOG + k] : 0.f;
    __nv_bfloat16 hi = __float2bfloat16(w);
    __nv_bfloat16 lo = __float2bfloat16(w - __bfloat162float(hi));
    g_Wb[gid] = hi;
    g_Wb[512 * KP + gid] = lo;
}

// ---------------- PTX helpers ----------------
#define CP_COMMIT()  asm volatile("cp.async.commit_group;")
#define CP_WAIT0()   asm volatile("cp.async.wait_group 0;")

#define LDSM4(r, addr) \
    asm volatile("ldmatrix.sync.aligned.m8n8.x4.shared.b16 {%0,%1,%2,%3}, [%4];" \
        : "=r"((r)[0]), "=r"((r)[1]), "=r"((r)[2]), "=r"((r)[3]) : "r"(addr))

#define MMA16816(d, a, b0, b1) \
    asm volatile("mma.sync.aligned.m16n8k16.row.col.f32.bf16.bf16.f32 " \
        "{%0,%1,%2,%3},{%4,%5,%6,%7},{%8,%9},{%0,%1,%2,%3};" \
        : "+f"((d)[0]), "+f"((d)[1]), "+f"((d)[2]), "+f"((d)[3]) \
        : "r"((a)[0]), "r"((a)[1]), "r"((a)[2]), "r"((a)[3]), "r"(b0), "r"(b1))

// coalesced modular stage of raw x rows covering one t-tile
__device__ __forceinline__ void stage_xs(uint32_t sdst, const float* xb, int t0) {
    int g0 = ((t0 - 169) & (S_ - 1)) * C_;
    for (int f = threadIdx.x; f < XSN; f += NTH) {
        int g = g0 + f;
        if (g >= S_ * C_) g -= S_ * C_;
        asm volatile("cp.async.ca.shared.global [%0], [%1], 4;"
                     :: "r"(sdst + (uint32_t)f * 4u), "l"(xb + g));
    }
}

__global__ __launch_bounds__(NTH, 1)
void conv_hmma_kernel(const float* __restrict__ x,
                      const float* __restrict__ bias,
                      float* __restrict__ out) {
    extern __shared__ char smem[];
    const uint32_t sb = (uint32_t)__cvta_generic_to_shared(smem);
    const int tid  = threadIdx.x;
    const int lane = tid & 31;
    const int wid  = tid >> 5;
    const int chunk = blockIdx.x & 3;
    const int slot  = blockIdx.x >> 2;
    const int ntiles = (NTILE - slot + NSLOT - 1) / NSLOT;

    float* biasS = (float*)(smem + SM_BIAS);
    int*   koffS = (int*)(smem + SM_KOFF);
    int*   khS   = (int*)(smem + SM_KH);

    for (int j = tid; j < OCH; j += NTH) biasS[j] = bias[chunk * OCH + j];
    for (int k = tid; k < KP; k += NTH) {
        int i = k / 3, h = k - 3 * i, m = i & 7, c = i >> 3;
        koffS[k] = (k < KLOG) ? ((h + KLOG - 24 * m) * C_ + c) : 0;
        khS[k]   = (k < KLOG) ? h : 3;       // sentinel -> always zero
    }

    // stage W (hi+lo) slice for this chunk: 2 x 128 rows x 22 x 16B
    {
        const char* wsrc = (const char*)g_Wb;
        for (int f = tid; f < 2 * 128 * 22; f += NTH) {
            int half = f / (128 * 22);
            int rem  = f - half * (128 * 22);
            int n = rem / 22, seg = rem - n * 22;
            const char* src = wsrc + (size_t)(half * 512 + chunk * OCH + n) * (KP * 2) + seg * 16;
            uint32_t dst = sb + (half ? SM_WLO : SM_WHI) + (uint32_t)n * ROWB + seg * 16;
            asm volatile("cp.async.cg.shared.global [%0], [%1], 16;"
                         :: "r"(dst), "l"(src));
        }
    }
    // stage xs for tile 0
    {
        int tl = slot;
        stage_xs(sb + SM_XS0, x + (size_t)(tl >> 4) * S_ * C_, (tl & 15) << 7);
    }
    CP_COMMIT();

    // per-lane ldmatrix base offsets
    const int warp_m = (wid & 3) * 32;
    const int warp_n = (wid >> 2) * 64;
    const int jT = lane >> 3;           // tile index within x4
    // A x4: tiles [m0,k0],[m0+8,k0],[m0,k0+8],[m0+8,k0+8]
    const uint32_t aOff = (uint32_t)(warp_m + ((jT & 1) << 3) + (lane & 7)) * ROWB
                        + (uint32_t)((jT >> 1) << 4);
    // B x4 #p covers ntiles 2p,2p+1: tiles [n0,k0],[n0,k0+8],[n0+8,k0],[n0+8,k0+8]
    uint32_t bOff[4];
    #pragma unroll
    for (int p = 0; p < 4; ++p)
        bOff[p] = (uint32_t)(warp_n + p * 16 + ((jT >> 1) << 3) + (lane & 7)) * ROWB
                + (uint32_t)((jT & 1) << 4);

    const int g  = lane >> 2;           // 0..7
    const int c2 = (lane & 3) * 2;      // 0,2,4,6
    uint32_t* zw = (uint32_t*)smem;     // word view of smem

    for (int n = 0; n < ntiles; ++n) {
        const int tl = slot + n * NSLOT;
        const int bb = tl >> 4;
        const int t0 = (tl & 15) << 7;

        CP_WAIT0();
        __syncthreads();                // xs[cur] ready; zs free (prev mma done)

        // prefetch xs for next tile into the other buffer
        if (n + 1 < ntiles) {
            int tl1 = slot + (n + 1) * NSLOT;
            stage_xs(((n + 1) & 1) ? (sb + SM_XS1) : (sb + SM_XS0),
                     x + (size_t)(tl1 >> 4) * S_ * C_, (tl1 & 15) << 7);
        }
        CP_COMMIT();

        // ---- build zs_hi / zs_lo: warp w owns rows w*16..w*16+15 ----
        {
            const float* xs = (const float*)(smem + ((n & 1) ? SM_XS1 : SM_XS0));
            for (int rr = 0; rr < 16; ++rr) {
                int r = wid * 16 + rr;
                int s = t0 + r - 1;
                uint32_t vm = 0;
                if (((s)     & (S_-1)) >= KLOG) vm |= 1;
                if (((s + 1) & (S_-1)) >= KLOG) vm |= 2;
                if (((s + 2) & (S_-1)) >= KLOG) vm |= 4;
                const float* xr = xs + r * C_;
                uint32_t* zH = zw + (SM_ZHI >> 2) + r * (ROWB >> 2);
                uint32_t* zL = zw + (SM_ZLO >> 2) + r * (ROWB >> 2);
                #pragma unroll
                for (int qs = 0; qs < 3; ++qs) {
                    int q = lane + qs * 32;
                    if (q < KP / 2) {
                        int k = 2 * q;
                        float f0 = ((vm >> khS[k])   & 1) ? xr[koffS[k]]   : 0.f;
                        float f1 = ((vm >> khS[k+1]) & 1) ? xr[koffS[k+1]] : 0.f;
                        __nv_bfloat16 h0 = __float2bfloat16(f0);
                        __nv_bfloat16 h1 = __float2bfloat16(f1);
                        __nv_bfloat16 l0 = __float2bfloat16(f0 - __bfloat162float(h0));
                        __nv_bfloat16 l1 = __float2bfloat16(f1 - __bfloat162float(h1));
                        zH[q] = (uint32_t)__bfloat16_as_ushort(h0)
                              | ((uint32_t)__bfloat16_as_ushort(h1) << 16);
                        zL[q] = (uint32_t)__bfloat16_as_ushort(l0)
                              | ((uint32_t)__bfloat16_as_ushort(l1) << 16);
                    }
                }
            }
        }
        __syncthreads();                // zs visible to all warps

        // ---- fused mma: one k-loop, 3 accumulation passes from shared frags ----
        float acc[2][8][4];
        #pragma unroll
        for (int mt = 0; mt < 2; ++mt)
            #pragma unroll
            for (int nt = 0; nt < 8; ++nt)
                #pragma unroll
                for (int q = 0; q < 4; ++q) acc[mt][nt][q] = 0.f;

        #pragma unroll 1
        for (int ks = 0; ks < NKS; ++ks) {
            uint32_t kb = (uint32_t)ks * 32u;
            uint32_t Ah0[4], Ah1[4], Al0[4], Al1[4];
            LDSM4(Ah0, sb + SM_ZHI + aOff + kb);
            LDSM4(Ah1, sb + SM_ZHI + aOff + 16 * ROWB + kb);
            LDSM4(Al0, sb + SM_ZLO + aOff + kb);
            LDSM4(Al1, sb + SM_ZLO + aOff + 16 * ROWB + kb);
            uint32_t Bh[4][4], Bl[4][4];
            #pragma unroll
            for (int p = 0; p < 4; ++p) {
                LDSM4(Bh[p], sb + SM_WHI + bOff[p] + kb);
                LDSM4(Bl[p], sb + SM_WLO + bOff[p] + kb);
            }
            #pragma unroll
            for (int nt = 0; nt < 8; ++nt) {
                uint32_t b0h = Bh[nt >> 1][(nt & 1) << 1];
                uint32_t b1h = Bh[nt >> 1][((nt & 1) << 1) + 1];
                uint32_t b0l = Bl[nt >> 1][(nt & 1) << 1];
                uint32_t b1l = Bl[nt >> 1][((nt & 1) << 1) + 1];
                MMA16816(acc[0][nt], Ah0, b0h, b1h);
                MMA16816(acc[1][nt], Ah1, b0h, b1h);
                MMA16816(acc[0][nt], Al0, b0h, b1h);
                MMA16816(acc[1][nt], Al1, b0h, b1h);
                MMA16816(acc[0][nt], Ah0, b0l, b1l);
                MMA16816(acc[1][nt], Ah1, b0l, b1l);
            }
        }

        // ---- epilogue: bias + store ----
        #pragma unroll
        for (int mt = 0; mt < 2; ++mt) {
            size_t row = (size_t)bb * S_ + t0 + warp_m + mt * 16 + g;
            #pragma unroll
            for (int nt = 0; nt < 8; ++nt) {
                int ncol = warp_n + nt * 8 + c2;
                float bi0 = biasS[ncol], bi1 = biasS[ncol + 1];
                float* p0 = out + row * O_ + chunk * OCH + ncol;
                *(float2*)p0 = make_float2(acc[mt][nt][0] + bi0,
                                           acc[mt][nt][1] + bi1);
                *(float2*)(p0 + 8 * O_) = make_float2(acc[mt][nt][2] + bi0,
                                                      acc[mt][nt][3] + bi1);
            }
        }
    }
}

extern "C" void kernel_launch(void* const* d_in, const int* in_sizes, int n_in,
                              void* d_out, int out_size) {
    const float* x    = (const float*)d_in[0];  // (32, 2048, 7)
    const float* W    = (const float*)d_in[1];  // (512, 56, 3)
    const float* bias = (const float*)d_in[2];  // (512,)
    float* out = (float*)d_out;                 // (32, 2048, 512)

    cudaFuncSetAttribute(conv_hmma_kernel,
                         cudaFuncAttributeMaxDynamicSharedMemorySize, SM_TOTAL);

    wsetup_kernel<<<(512 * KP + 255) / 256, 256>>>(W);
    conv_hmma_kernel<<<NSLOT * NCHUNK, NTH, SM_TOTAL>>>(x, bias, out);
}

// round 10
// speedup vs baseline: 2.4075x; 1.3370x over previous
#include <cuda_runtime.h>
#include <cuda_bf16.h>
#include <cstdint>
#include <cstddef>

// ---------------- problem constants ----------------
#define B_    32
#define S_    2048
#define C_    7
#define O_    512
#define KLOG  168          // real K, k = i*3+h, i = c*8+m
#define KP    176          // padded K (11 ksteps of 16)
#define NKS   11
#define TT    128          // t per tile (M)
#define OCH   128          // o per chunk (N)
#define NCHUNK 4
#define NSLOT 37           // 37*4 = 148 persistent CTAs
#define NTILE 512          // t-tiles per chunk (32 b * 16)
#define NTH   256

#define ROWB  368          // smem bf16 row stride in bytes (16B-aligned, conflict-free)
#define GROWW (KP/2)       // gmem z row in words (88)

// ---------------- smem byte layout (total ~185KB) ----------------
#define SM_BIAS  0                      // 512B
#define SM_AHI   512                    // 128*368 = 47104
#define SM_ALO   (SM_AHI + 47104)
#define SM_WHI   (SM_ALO + 47104)
#define SM_WLO   (SM_WHI + 47104)
#define SM_TOTAL (SM_WLO + 47104)       // 188928

// W pre-split: [hi|lo][o=512][k=176] bf16
__device__ __nv_bfloat16 g_Wb[2 * 512 * KP];
// z materialized: [hi|lo][b*2048+t][176] bf16  (46 MB scratch)
__device__ uint32_t g_z[2][B_ * S_ * GROWW];

__global__ void wsetup_kernel(const float* __restrict__ W) {
    int gid = blockIdx.x * blockDim.x + threadIdx.x;
    if (gid >= 512 * KP) return;
    int o = gid / KP, k = gid % KP;
    float w = (k < KLOG) ? W[o * KLOG + k] : 0.f;
    __nv_bfloat16 hi = __float2bfloat16(w);
    __nv_bfloat16 lo = __float2bfloat16(w - __bfloat162float(hi));
    g_Wb[gid] = hi;
    g_Wb[512 * KP + gid] = lo;
}

// build z (hi/lo bf16 pairs) for every (b, t, kpair)
__global__ void zprep_kernel(const float* __restrict__ x) {
    int gid = blockIdx.x * blockDim.x + threadIdx.x;
    if (gid >= B_ * S_ * GROWW) return;
    int q  = gid % GROWW;
    int bt = gid / GROWW;
    int tt = bt & (S_ - 1);
    int b  = bt >> 11;
    uint32_t hw = 0, lw = 0;
    #pragma unroll
    for (int half = 0; half < 2; ++half) {
        int k = 2 * q + half;
        float val = 0.f;
        if (k < KLOG) {
            int i = k / 3, h = k - 3 * i, m = i & 7, c = i >> 3;
            int s = (tt - 1 + h) & (S_ - 1);
            if (s >= KLOG)
                val = __ldg(&x[((size_t)b * S_ + (s - 24 * m)) * C_ + c]);
        }
        __nv_bfloat16 hi = __float2bfloat16(val);
        __nv_bfloat16 lo = __float2bfloat16(val - __bfloat162float(hi));
        hw |= (uint32_t)__bfloat16_as_ushort(hi) << (16 * half);
        lw |= (uint32_t)__bfloat16_as_ushort(lo) << (16 * half);
    }
    g_z[0][gid] = hw;
    g_z[1][gid] = lw;
}

// ---------------- PTX helpers ----------------
#define CP_COMMIT()  asm volatile("cp.async.commit_group;")
#define CP_WAIT0()   asm volatile("cp.async.wait_group 0;")
#define PAIR_BAR(id) asm volatile("bar.sync %0, 64;" :: "r"(id) : "memory")

#define LDSM4(r, addr) \
    asm volatile("ldmatrix.sync.aligned.m8n8.x4.shared.b16 {%0,%1,%2,%3}, [%4];" \
        : "=r"((r)[0]), "=r"((r)[1]), "=r"((r)[2]), "=r"((r)[3]) : "r"(addr))

#define MMA16816(d, a, b0, b1) \
    asm volatile("mma.sync.aligned.m16n8k16.row.col.f32.bf16.bf16.f32 " \
        "{%0,%1,%2,%3},{%4,%5,%6,%7},{%8,%9},{%0,%1,%2,%3};" \
        : "+f"((d)[0]), "+f"((d)[1]), "+f"((d)[2]), "+f"((d)[3]) \
        : "r"((a)[0]), "r"((a)[1]), "r"((a)[2]), "r"((a)[3]), "r"(b0), "r"(b1))

// prefetch of one half (hi or lo) of the pair's 32 A rows for one tile
__device__ __forceinline__ void prefetch_A_half(uint32_t sb, int warp_m, int lane,
                                                int half, int bb, int t0) {
    size_t grow0 = (size_t)bb * S_ + t0 + warp_m;
    const uint32_t base = sb + (half ? SM_ALO : SM_AHI);
    const uint32_t* src0 = g_z[half];
    #pragma unroll 1
    for (int j = 0; j < 22; ++j) {
        int f = j * 32 + lane;
        int row = f / 22;
        int seg = f - row * 22;
        const uint32_t* src = src0 + (grow0 + row) * GROWW + seg * 4;
        uint32_t dst = base + (uint32_t)(warp_m + row) * ROWB + seg * 16;
        asm volatile("cp.async.cg.shared.global [%0], [%1], 16;"
                     :: "r"(dst), "l"(src));
    }
}

__global__ __launch_bounds__(NTH, 1)
void conv_hmma_kernel(const float* __restrict__ bias,
                      float* __restrict__ out) {
    extern __shared__ char smem[];
    const uint32_t sb = (uint32_t)__cvta_generic_to_shared(smem);
    const int tid  = threadIdx.x;
    const int lane = tid & 31;
    const int wid  = tid >> 5;
    const int chunk = blockIdx.x & 3;
    const int slot  = blockIdx.x >> 2;
    const int ntiles = (NTILE - slot + NSLOT - 1) / NSLOT;

    float* biasS = (float*)(smem + SM_BIAS);
    for (int j = tid; j < OCH; j += NTH) biasS[j] = bias[chunk * OCH + j];

    // stage W (hi+lo) slice for this chunk: 2 x 128 rows x 22 x 16B
    {
        const char* wsrc = (const char*)g_Wb;
        for (int f = tid; f < 2 * 128 * 22; f += NTH) {
            int half = f / (128 * 22);
            int rem  = f - half * (128 * 22);
            int n = rem / 22, seg = rem - n * 22;
            const char* src = wsrc + (size_t)(half * 512 + chunk * OCH + n) * (KP * 2) + seg * 16;
            uint32_t dst = sb + (half ? SM_WLO : SM_WHI) + (uint32_t)n * ROWB + seg * 16;
            asm volatile("cp.async.cg.shared.global [%0], [%1], 16;"
                         :: "r"(dst), "l"(src));
        }
    }

    const int warp_m = (wid & 3) * 32;     // warps w and w+4 SHARE these A rows
    const int warp_n = (wid >> 2) * 64;
    const int ahalf  = wid >> 2;           // pair split: w loads hi, w+4 loads lo
    const int barid  = 1 + (wid & 3);      // pair-scoped named barrier

    // prefetch A for tile 0 (each pair member loads its half)
    {
        int tl = slot;
        prefetch_A_half(sb, warp_m, lane, ahalf, tl >> 4, (tl & 15) << 7);
    }
    CP_COMMIT();
    CP_WAIT0();
    __syncthreads();          // W + bias + everyone's A(0) visible

    // per-lane ldmatrix offsets
    const int jT = lane >> 3;
    const uint32_t aOff = (uint32_t)(warp_m + ((jT & 1) << 3) + (lane & 7)) * ROWB
                        + (uint32_t)((jT >> 1) << 4);
    uint32_t bOff[4];
    #pragma unroll
    for (int p = 0; p < 4; ++p)
        bOff[p] = (uint32_t)(warp_n + p * 16 + ((jT >> 1) << 3) + (lane & 7)) * ROWB
                + (uint32_t)((jT & 1) << 4);

    const int g  = lane >> 2;
    const int c2 = (lane & 3) * 2;

    for (int n = 0; n < ntiles; ++n) {
        const int tl = slot + n * NSLOT;
        const int bb = tl >> 4;
        const int t0 = (tl & 15) << 7;

        if (n) {
            CP_WAIT0();       // own half of A(n) landed
            PAIR_BAR(barid);  // partner's half landed too -> visible to pair
        }

        float acc[2][8][4];
        #pragma unroll
        for (int mt = 0; mt < 2; ++mt)
            #pragma unroll
            for (int nt = 0; nt < 8; ++nt)
                #pragma unroll
                for (int q = 0; q < 4; ++q) acc[mt][nt][q] = 0.f;

        #pragma unroll 1
        for (int ks = 0; ks < NKS; ++ks) {
            uint32_t kb = (uint32_t)ks * 32u;
            uint32_t Ah0[4], Ah1[4], Al0[4], Al1[4];
            LDSM4(Ah0, sb + SM_AHI + aOff + kb);
            LDSM4(Ah1, sb + SM_AHI + aOff + 16 * ROWB + kb);
            LDSM4(Al0, sb + SM_ALO + aOff + kb);
            LDSM4(Al1, sb + SM_ALO + aOff + 16 * ROWB + kb);
            uint32_t Bh[4][4], Bl[4][4];
            #pragma unroll
            for (int p = 0; p < 4; ++p) {
                LDSM4(Bh[p], sb + SM_WHI + bOff[p] + kb);
                LDSM4(Bl[p], sb + SM_WLO + bOff[p] + kb);
            }
            #pragma unroll
            for (int nt = 0; nt < 8; ++nt) {
                uint32_t b0h = Bh[nt >> 1][(nt & 1) << 1];
                uint32_t b1h = Bh[nt >> 1][((nt & 1) << 1) + 1];
                uint32_t b0l = Bl[nt >> 1][(nt & 1) << 1];
                uint32_t b1l = Bl[nt >> 1][((nt & 1) << 1) + 1];
                MMA16816(acc[0][nt], Ah0, b0h, b1h);
                MMA16816(acc[1][nt], Ah1, b0h, b1h);
                MMA16816(acc[0][nt], Al0, b0h, b1h);
                MMA16816(acc[1][nt], Al1, b0h, b1h);
                MMA16816(acc[0][nt], Ah0, b0l, b1l);
                MMA16816(acc[1][nt], Ah1, b0l, b1l);
            }
        }

        // both pair members done READING A(n) before anyone overwrites it
        PAIR_BAR(barid);

        if (n + 1 < ntiles) {
            int tl1 = slot + (n + 1) * NSLOT;
            prefetch_A_half(sb, warp_m, lane, ahalf, tl1 >> 4, (tl1 & 15) << 7);
        }
        CP_COMMIT();

        // ---- epilogue: bias + store (overlaps the A prefetch) ----
        #pragma unroll
        for (int mt = 0; mt < 2; ++mt) {
            size_t row = (size_t)bb * S_ + t0 + warp_m + mt * 16 + g;
            #pragma unroll
            for (int nt = 0; nt < 8; ++nt) {
                int ncol = warp_n + nt * 8 + c2;
                float bi0 = biasS[ncol], bi1 = biasS[ncol + 1];
                float* p0 = out + row * O_ + chunk * OCH + ncol;
                *(float2*)p0 = make_float2(acc[mt][nt][0] + bi0,
                                           acc[mt][nt][1] + bi1);
                *(float2*)(p0 + 8 * O_) = make_float2(acc[mt][nt][2] + bi0,
                                                      acc[mt][nt][3] + bi1);
            }
        }
    }
}

extern "C" void kernel_launch(void* const* d_in, const int* in_sizes, int n_in,
                              void* d_out, int out_size) {
    const float* x    = (const float*)d_in[0];  // (32, 2048, 7)
    const float* W    = (const float*)d_in[1];  // (512, 56, 3)
    const float* bias = (const float*)d_in[2];  // (512,)
    float* out = (float*)d_out;                 // (32, 2048, 512)

    cudaFuncSetAttribute(conv_hmma_kernel,
                         cudaFuncAttributeMaxDynamicSharedMemorySize, SM_TOTAL);

    wsetup_kernel<<<(512 * KP + 255) / 256, 256>>>(W);
    zprep_kernel<<<(B_ * S_ * GROWW + 255) / 256, 256>>>(x);
    conv_hmma_kernel<<<NSLOT * NCHUNK, NTH, SM_TOTAL>>>(bias, out);
}